// round 1
// baseline (speedup 1.0000x reference)
#include <cuda_runtime.h>
#include <math.h>

// Problem constants (validated/derived from in_sizes at launch)
#define N_NODES 20000
#define N_EDGES 320000
#define IN_CH   256
#define HIDHEAD 256   // HEADS*HID
#define HEADS   8
#define HID     32
#define NCLS    16

#define ET_MAX  (N_EDGES + N_NODES)

// ---------------- scratch (device globals; allocation-free) ----------------
__device__ float g_h1  [(size_t)N_NODES * HIDHEAD];   // x @ W1
__device__ float g_out1[(size_t)N_NODES * HIDHEAD];   // layer1 output (post-ELU)
__device__ float g_h2  [(size_t)N_NODES * NCLS];      // out1 @ W2
__device__ float g_as1 [N_NODES * HEADS];
__device__ float g_ad1 [N_NODES * HEADS];
__device__ float g_as2 [N_NODES];
__device__ float g_ad2 [N_NODES];
__device__ int   g_deg [N_NODES];
__device__ int   g_start[N_NODES + 1];
__device__ int   g_cursor[N_NODES];
__device__ int   g_csr_src[ET_MAX];
__device__ float g_csr_ew [ET_MAX];

// ---------------- CSR build ----------------
__global__ void zero_deg_k(int n) {
    int i = blockIdx.x * blockDim.x + threadIdx.x;
    if (i < n) g_deg[i] = 0;
}

__global__ void hist_k(const int* __restrict__ ei, int E, int ET) {
    int e = blockIdx.x * blockDim.x + threadIdx.x;
    if (e >= ET) return;
    int dst = (e < E) ? ei[E + e] : (e - E);
    atomicAdd(&g_deg[dst], 1);
}

// single-block scan: each thread owns a contiguous chunk
__global__ void scan_k(int n) {
    __shared__ int sh[1024];
    int tid = threadIdx.x;
    int chunk = (n + 1023) / 1024;
    int b = tid * chunk;
    int e = b + chunk; if (e > n) e = n;
    int s = 0;
    for (int i = b; i < e; i++) s += g_deg[i];
    sh[tid] = s;
    __syncthreads();
    for (int off = 1; off < 1024; off <<= 1) {
        int t = (tid >= off) ? sh[tid - off] : 0;
        __syncthreads();
        sh[tid] += t;
        __syncthreads();
    }
    int run = sh[tid] - s;  // exclusive prefix
    for (int i = b; i < e; i++) {
        g_start[i] = run;
        g_cursor[i] = run;
        run += g_deg[i];
    }
    if (tid == 1023) g_start[n] = sh[1023];
}

__global__ void scatter_k(const int* __restrict__ ei, const float* __restrict__ ew,
                          int E, int ET) {
    int e = blockIdx.x * blockDim.x + threadIdx.x;
    if (e >= ET) return;
    int src, dst; float w;
    if (e < E) { src = ei[e]; dst = ei[E + e]; w = ew[e]; }
    else       { src = e - E; dst = e - E;     w = 1.0f; }
    int pos = atomicAdd(&g_cursor[dst], 1);
    g_csr_src[pos] = src;
    g_csr_ew [pos] = w;
}

// ---------------- GEMM1: C[N,256] = A[N,256] @ B[256,256] ----------------
#define BM 128
#define BN 64
#define BK 16
__global__ void sgemm_k(const float* __restrict__ A, const float* __restrict__ B,
                        float* __restrict__ C, int N, int K, int M) {
    __shared__ float As[BK][BM + 4];
    __shared__ float Bs[BK][BN + 4];
    int tx = threadIdx.x, ty = threadIdx.y;
    int tid = ty * 16 + tx;
    int row0 = blockIdx.x * BM;
    int col0 = blockIdx.y * BN;
    float acc[8][4];
#pragma unroll
    for (int i = 0; i < 8; i++)
#pragma unroll
        for (int j = 0; j < 4; j++) acc[i][j] = 0.f;

    for (int kt = 0; kt < K; kt += BK) {
        // A tile: 128 rows x 16 k  (512 float4, 2 per thread)
#pragma unroll
        for (int l = 0; l < 2; l++) {
            int idx = tid + l * 256;
            int r = idx >> 2;
            int kq = (idx & 3) * 4;
            int grow = row0 + r;
            float4 v = make_float4(0.f, 0.f, 0.f, 0.f);
            if (grow < N) v = *(const float4*)(A + (size_t)grow * K + kt + kq);
            As[kq + 0][r] = v.x; As[kq + 1][r] = v.y;
            As[kq + 2][r] = v.z; As[kq + 3][r] = v.w;
        }
        // B tile: 16 k x 64 cols (256 float4, 1 per thread)
        {
            int k = tid >> 4;
            int cq = (tid & 15) * 4;
            float4 v = *(const float4*)(B + (size_t)(kt + k) * M + col0 + cq);
            Bs[k][cq + 0] = v.x; Bs[k][cq + 1] = v.y;
            Bs[k][cq + 2] = v.z; Bs[k][cq + 3] = v.w;
        }
        __syncthreads();
#pragma unroll
        for (int k = 0; k < BK; k++) {
            float a[8], b[4];
#pragma unroll
            for (int i = 0; i < 8; i++) a[i] = As[k][ty * 8 + i];
#pragma unroll
            for (int j = 0; j < 4; j++) b[j] = Bs[k][tx * 4 + j];
#pragma unroll
            for (int i = 0; i < 8; i++)
#pragma unroll
                for (int j = 0; j < 4; j++) acc[i][j] = fmaf(a[i], b[j], acc[i][j]);
        }
        __syncthreads();
    }
#pragma unroll
    for (int i = 0; i < 8; i++) {
        int grow = row0 + ty * 8 + i;
        if (grow < N) {
#pragma unroll
            for (int j = 0; j < 4; j++)
                C[(size_t)grow * M + col0 + tx * 4 + j] = acc[i][j];
        }
    }
}

// ---------------- attention coefficients, layer 1 ----------------
__global__ void att1_k(const float* __restrict__ h1, const float* __restrict__ asw,
                       const float* __restrict__ adw, int N) {
    int t = blockIdx.x * blockDim.x + threadIdx.x;
    if (t >= N * HEADS) return;
    int n = t >> 3, h = t & 7;
    const float4* hp = (const float4*)(h1 + (size_t)n * HIDHEAD + h * HID);
    const float4* sp = (const float4*)(asw + h * HID);
    const float4* dp = (const float4*)(adw + h * HID);
    float s = 0.f, d = 0.f;
#pragma unroll
    for (int q = 0; q < 8; q++) {
        float4 hv = hp[q], sv = sp[q], dv = dp[q];
        s += hv.x * sv.x + hv.y * sv.y + hv.z * sv.z + hv.w * sv.w;
        d += hv.x * dv.x + hv.y * dv.y + hv.z * dv.z + hv.w * dv.w;
    }
    g_as1[t] = s;
    g_ad1[t] = d;
}

// ---------------- layer-1 softmax aggregation (1 warp / dst node) ----------------
__global__ void agg1_k(const float* __restrict__ b1, int N) {
    int warp = (blockIdx.x * blockDim.x + threadIdx.x) >> 5;
    if (warp >= N) return;
    int lane = threadIdx.x & 31;
    int s = g_start[warp], e = g_start[warp + 1];
    float adv = (lane < HEADS) ? g_ad1[warp * HEADS + lane] : 0.f;

    // pass 1: per-head max (lanes 0..7 own one head each)
    float m = -INFINITY;
    for (int i = s; i < e; i++) {
        int src = g_csr_src[i];
        float w = g_csr_ew[i];
        if (lane < HEADS) {
            float t = g_as1[src * HEADS + lane] + adv;
            t = (t > 0.f ? t : 0.2f * t) * w;
            m = fmaxf(m, t);
        }
    }

    // pass 2: exp-weighted gather
    float acc[8];
#pragma unroll
    for (int k = 0; k < 8; k++) acc[k] = 0.f;
    float den = 0.f;
    for (int i = s; i < e; i++) {
        int src = g_csr_src[i];
        float w = g_csr_ew[i];
        float wexp = 0.f;
        if (lane < HEADS) {
            float t = g_as1[src * HEADS + lane] + adv;
            t = (t > 0.f ? t : 0.2f * t) * w;
            wexp = expf(t - m);
        }
        den += wexp;
        const float* hp = g_h1 + (size_t)src * HIDHEAD;
#pragma unroll
        for (int k = 0; k < 8; k++) {
            float wk = __shfl_sync(0xffffffffu, wexp, k);
            acc[k] = fmaf(wk, hp[lane + 32 * k], acc[k]);
        }
    }

    // epilogue: divide, bias, ELU
#pragma unroll
    for (int k = 0; k < 8; k++) {
        float dk = __shfl_sync(0xffffffffu, den, k);
        int c = lane + 32 * k;
        float v = acc[k] / (dk + 1e-16f) + b1[c];
        v = (v > 0.f) ? v : (expf(v) - 1.f);
        g_out1[(size_t)warp * HIDHEAD + c] = v;
    }
}

// ---------------- GEMM2: h2[N,16] = out1[N,256] @ W2[256,16] ----------------
__global__ void gemm16_k(const float* __restrict__ A, const float* __restrict__ W,
                         float* __restrict__ C, int N) {
    __shared__ float Bs[256 * 16];
    __shared__ float As[16 * 256];
    int tid = threadIdx.x;
    for (int i = tid; i < 4096; i += 256) Bs[i] = W[i];
    int n0 = blockIdx.x * 16;
    for (int i = tid; i < 4096; i += 256) {
        int r = i >> 8;
        As[i] = (n0 + r < N) ? A[(size_t)(n0 + r) * 256 + (i & 255)] : 0.f;
    }
    __syncthreads();
    int r = tid >> 4, c = tid & 15;
    float acc = 0.f;
#pragma unroll 8
    for (int k = 0; k < 256; k++) acc = fmaf(As[r * 256 + k], Bs[k * 16 + c], acc);
    if (n0 + r < N) C[(size_t)(n0 + r) * 16 + c] = acc;
}

// ---------------- attention coefficients, layer 2 ----------------
__global__ void att2_k(const float* __restrict__ h2, const float* __restrict__ asw,
                       const float* __restrict__ adw, int N) {
    int n = blockIdx.x * blockDim.x + threadIdx.x;
    if (n >= N) return;
    const float4* hp = (const float4*)(h2 + (size_t)n * NCLS);
    const float4* sp = (const float4*)asw;
    const float4* dp = (const float4*)adw;
    float s = 0.f, d = 0.f;
#pragma unroll
    for (int q = 0; q < 4; q++) {
        float4 hv = hp[q], sv = sp[q], dv = dp[q];
        s += hv.x * sv.x + hv.y * sv.y + hv.z * sv.z + hv.w * sv.w;
        d += hv.x * dv.x + hv.y * dv.y + hv.z * dv.z + hv.w * dv.w;
    }
    g_as2[n] = s;
    g_ad2[n] = d;
}

// ---------------- layer-2 softmax aggregation (1 warp / dst node) ----------------
__global__ void agg2_k(const float* __restrict__ b2, float* __restrict__ out, int N) {
    int warp = (blockIdx.x * blockDim.x + threadIdx.x) >> 5;
    if (warp >= N) return;
    int lane = threadIdx.x & 31;
    int s = g_start[warp], e = g_start[warp + 1];
    float adv = g_ad2[warp];

    float m = -INFINITY;
    for (int i = s; i < e; i++) {
        float t = g_as2[g_csr_src[i]] + adv;
        t = (t > 0.f ? t : 0.2f * t) * g_csr_ew[i];
        m = fmaxf(m, t);
    }
    float acc = 0.f, den = 0.f;
    for (int i = s; i < e; i++) {
        int src = g_csr_src[i];
        float t = g_as2[src] + adv;
        t = (t > 0.f ? t : 0.2f * t) * g_csr_ew[i];
        float w = expf(t - m);
        den += w;
        if (lane < NCLS) acc = fmaf(w, g_h2[(size_t)src * NCLS + lane], acc);
    }
    if (lane < NCLS) out[(size_t)warp * NCLS + lane] = acc / (den + 1e-16f) + b2[lane];
}

// ---------------- launch ----------------
extern "C" void kernel_launch(void* const* d_in, const int* in_sizes, int n_in,
                              void* d_out, int out_size) {
    const float* x   = (const float*)d_in[0];
    const int*   ei  = (const int*)  d_in[1];
    const float* ew  = (const float*)d_in[2];
    const float* W1  = (const float*)d_in[3];
    const float* as1 = (const float*)d_in[4];
    const float* ad1 = (const float*)d_in[5];
    const float* b1  = (const float*)d_in[6];
    const float* W2  = (const float*)d_in[7];
    const float* as2 = (const float*)d_in[8];
    const float* ad2 = (const float*)d_in[9];
    const float* b2  = (const float*)d_in[10];
    float* out = (float*)d_out;

    int N  = in_sizes[0] / IN_CH;     // 20000
    int E  = in_sizes[2];             // 320000
    int ET = E + N;                   // with self-loops

    // scratch pointers
    float *h1, *out1, *h2;
    cudaGetSymbolAddress((void**)&h1,   g_h1);
    cudaGetSymbolAddress((void**)&out1, g_out1);
    cudaGetSymbolAddress((void**)&h2,   g_h2);

    // --- CSR build ---
    zero_deg_k<<<(N + 255) / 256, 256>>>(N);
    hist_k<<<(ET + 255) / 256, 256>>>(ei, E, ET);
    scan_k<<<1, 1024>>>(N);
    scatter_k<<<(ET + 255) / 256, 256>>>(ei, ew, E, ET);

    // --- layer 1 ---
    {
        dim3 grid((N + BM - 1) / BM, HIDHEAD / BN);
        dim3 blk(16, 16);
        sgemm_k<<<grid, blk>>>(x, W1, h1, N, IN_CH, HIDHEAD);
    }
    att1_k<<<(N * HEADS + 255) / 256, 256>>>(h1, as1, ad1, N);
    agg1_k<<<(N + 7) / 8, 256>>>(b1, N);   // 8 warps / block

    // --- layer 2 ---
    gemm16_k<<<(N + 15) / 16, 256>>>(out1, W2, h2, N);
    att2_k<<<(N + 255) / 256, 256>>>(h2, as2, ad2, N);
    agg2_k<<<(N + 7) / 8, 256>>>(b2, out, N);
}

// round 2
// speedup vs baseline: 1.0564x; 1.0564x over previous
#include <cuda_runtime.h>
#include <math.h>

#define N_NODES 20000
#define N_EDGES 320000
#define IN_CH   256
#define HIDHEAD 256   // HEADS*HID
#define HEADS   8
#define HID     32
#define NCLS    16
#define ET_MAX  (N_EDGES + N_NODES)

// ---------------- scratch (device globals; allocation-free) ----------------
__device__ float g_h1  [(size_t)N_NODES * HIDHEAD];   // x @ W1
__device__ float g_h2  [(size_t)N_NODES * NCLS];      // layer2 pre-aggregation features
__device__ float g_as1 [N_NODES * HEADS];
__device__ float g_ad1 [N_NODES * HEADS];
__device__ float g_as2 [N_NODES];
__device__ float g_ad2 [N_NODES];
__device__ int   g_deg [N_NODES];
__device__ int   g_start[N_NODES + 1];
__device__ int   g_cursor[N_NODES];
__device__ int2  g_csr [ET_MAX];                      // {src, bitcast(ew)}

// ---------------- CSR build ----------------
__global__ void zero_deg_k(int n) {
    int i = blockIdx.x * blockDim.x + threadIdx.x;
    if (i < n) g_deg[i] = 0;
}

__global__ void hist_k(const int* __restrict__ ei, int E, int ET) {
    int e = blockIdx.x * blockDim.x + threadIdx.x;
    if (e >= ET) return;
    int dst = (e < E) ? ei[E + e] : (e - E);
    atomicAdd(&g_deg[dst], 1);
}

// single-block scan: each thread owns a contiguous chunk
__global__ void scan_k(int n) {
    __shared__ int sh[1024];
    int tid = threadIdx.x;
    int chunk = (n + 1023) / 1024;
    int b = tid * chunk;
    int e = b + chunk; if (e > n) e = n;
    int s = 0;
    for (int i = b; i < e; i++) s += g_deg[i];
    sh[tid] = s;
    __syncthreads();
    for (int off = 1; off < 1024; off <<= 1) {
        int t = (tid >= off) ? sh[tid - off] : 0;
        __syncthreads();
        sh[tid] += t;
        __syncthreads();
    }
    int run = sh[tid] - s;  // exclusive prefix
    for (int i = b; i < e; i++) {
        g_start[i] = run;
        g_cursor[i] = run;
        run += g_deg[i];
    }
    if (tid == 1023) g_start[n] = sh[1023];
}

__global__ void scatter_k(const int* __restrict__ ei, const float* __restrict__ ew,
                          int E, int ET) {
    int e = blockIdx.x * blockDim.x + threadIdx.x;
    if (e >= ET) return;
    int src, dst; float w;
    if (e < E) { src = ei[e]; dst = ei[E + e]; w = ew[e]; }
    else       { src = e - E; dst = e - E;     w = 1.0f; }
    int pos = atomicAdd(&g_cursor[dst], 1);
    g_csr[pos] = make_int2(src, __float_as_int(w));
}

// ---------------- GEMM1: C[N,256] = A[N,256] @ B[256,256] ----------------
// 128x128x8 tile, 256 threads, 8x8 per thread, float4 LDS
__global__ void sgemm_k(const float* __restrict__ A, const float* __restrict__ B,
                        float* __restrict__ C, int N) {
    __shared__ float As[8][132];
    __shared__ float Bs[8][132];
    int tid = threadIdx.x;
    int tx = tid & 15, ty = tid >> 4;
    int row0 = blockIdx.x * 128;
    int col0 = blockIdx.y * 128;
    float acc[8][8];
#pragma unroll
    for (int i = 0; i < 8; i++)
#pragma unroll
        for (int j = 0; j < 8; j++) acc[i][j] = 0.f;

    int ar = tid >> 1, akq = (tid & 1) * 4;
    int bk = tid >> 5, bcq = (tid & 31) * 4;

    for (int kt = 0; kt < 256; kt += 8) {
        float4 av = make_float4(0.f, 0.f, 0.f, 0.f);
        if (row0 + ar < N) av = *(const float4*)(A + (size_t)(row0 + ar) * 256 + kt + akq);
        As[akq + 0][ar] = av.x; As[akq + 1][ar] = av.y;
        As[akq + 2][ar] = av.z; As[akq + 3][ar] = av.w;

        float4 bv = *(const float4*)(B + (size_t)(kt + bk) * 256 + col0 + bcq);
        *(float4*)&Bs[bk][bcq] = bv;
        __syncthreads();

#pragma unroll
        for (int k = 0; k < 8; k++) {
            float4 a0 = *(float4*)&As[k][ty * 8];
            float4 a1 = *(float4*)&As[k][ty * 8 + 4];
            float4 b0 = *(float4*)&Bs[k][tx * 8];
            float4 b1 = *(float4*)&Bs[k][tx * 8 + 4];
            float a[8] = {a0.x, a0.y, a0.z, a0.w, a1.x, a1.y, a1.z, a1.w};
            float b[8] = {b0.x, b0.y, b0.z, b0.w, b1.x, b1.y, b1.z, b1.w};
#pragma unroll
            for (int i = 0; i < 8; i++)
#pragma unroll
                for (int j = 0; j < 8; j++) acc[i][j] = fmaf(a[i], b[j], acc[i][j]);
        }
        __syncthreads();
    }
#pragma unroll
    for (int i = 0; i < 8; i++) {
        int grow = row0 + ty * 8 + i;
        if (grow < N) {
            *(float4*)(C + (size_t)grow * 256 + col0 + tx * 8)     =
                make_float4(acc[i][0], acc[i][1], acc[i][2], acc[i][3]);
            *(float4*)(C + (size_t)grow * 256 + col0 + tx * 8 + 4) =
                make_float4(acc[i][4], acc[i][5], acc[i][6], acc[i][7]);
        }
    }
}

// ---------------- attention coefficients, layer 1 ----------------
__global__ void att1_k(const float* __restrict__ h1, const float* __restrict__ asw,
                       const float* __restrict__ adw, int N) {
    int t = blockIdx.x * blockDim.x + threadIdx.x;
    if (t >= N * HEADS) return;
    int n = t >> 3, h = t & 7;
    const float4* hp = (const float4*)(h1 + (size_t)n * HIDHEAD + h * HID);
    const float4* sp = (const float4*)(asw + h * HID);
    const float4* dp = (const float4*)(adw + h * HID);
    float s = 0.f, d = 0.f;
#pragma unroll
    for (int q = 0; q < 8; q++) {
        float4 hv = hp[q], sv = sp[q], dv = dp[q];
        s += hv.x * sv.x + hv.y * sv.y + hv.z * sv.z + hv.w * sv.w;
        d += hv.x * dv.x + hv.y * dv.y + hv.z * dv.z + hv.w * dv.w;
    }
    g_as1[t] = s;
    g_ad1[t] = d;
}

// ---------------- layer-1 aggregation fused with GEMM2 + att2 ----------------
// 1 warp per dst node. Single pass (no max subtraction; logits are O(1), exp safe).
// After aggregation the warp holds the full 256-wide out1 row in registers:
// lane owns cols [lane*4 .. lane*4+3] and [128+lane*4 .. 128+lane*4+3].
// GEMM2 (256->16) is done against smem-resident transposed W2, butterfly-reduced.
__global__ void agg1_k(const float* __restrict__ b1, const float* __restrict__ W2,
                       const float* __restrict__ as2w, const float* __restrict__ ad2w,
                       int N) {
    __shared__ float sW2t[NCLS * 256];   // [m][c], 16KB
    __shared__ float sas2[NCLS], sad2[NCLS];
    int tid = threadIdx.x;
    for (int i = tid; i < 256 * NCLS; i += 256) {
        int c = i >> 4, m = i & 15;
        sW2t[m * 256 + c] = W2[i];
    }
    if (tid < NCLS) { sas2[tid] = as2w[tid]; sad2[tid] = ad2w[tid]; }
    __syncthreads();

    int warp = blockIdx.x * 8 + (tid >> 5);
    if (warp >= N) return;
    int lane = tid & 31;
    int s = g_start[warp], e = g_start[warp + 1];
    float adv = (lane < HEADS) ? g_ad1[warp * HEADS + lane] : 0.f;
    int h0 = lane >> 3;

    float4 acc0 = make_float4(0.f, 0.f, 0.f, 0.f);
    float4 acc1 = make_float4(0.f, 0.f, 0.f, 0.f);
    float den = 0.f;

    for (int i = s; i < e; i++) {
        int2 se = g_csr[i];
        int src = se.x;
        float w = __int_as_float(se.y);
        float wexp = 0.f;
        if (lane < HEADS) {
            float t = g_as1[src * HEADS + lane] + adv;
            t = (t > 0.f ? t : 0.2f * t) * w;
            wexp = __expf(t);
        }
        den += wexp;
        const float4* hp = (const float4*)(g_h1 + (size_t)src * HIDHEAD);
        float4 v0 = hp[lane];
        float4 v1 = hp[lane + 32];
        float w0 = __shfl_sync(0xffffffffu, wexp, h0);
        float w1 = __shfl_sync(0xffffffffu, wexp, 4 + h0);
        acc0.x = fmaf(w0, v0.x, acc0.x); acc0.y = fmaf(w0, v0.y, acc0.y);
        acc0.z = fmaf(w0, v0.z, acc0.z); acc0.w = fmaf(w0, v0.w, acc0.w);
        acc1.x = fmaf(w1, v1.x, acc1.x); acc1.y = fmaf(w1, v1.y, acc1.y);
        acc1.z = fmaf(w1, v1.z, acc1.z); acc1.w = fmaf(w1, v1.w, acc1.w);
    }

    // finalize: softmax divide, bias, ELU
    float d0 = __shfl_sync(0xffffffffu, den, h0);
    float d1 = __shfl_sync(0xffffffffu, den, 4 + h0);
    float inv0 = 1.f / (d0 + 1e-16f);
    float inv1 = 1.f / (d1 + 1e-16f);
    float4 bb0 = ((const float4*)b1)[lane];
    float4 bb1 = ((const float4*)b1)[lane + 32];
    float o[8];
    o[0] = acc0.x * inv0 + bb0.x;  o[1] = acc0.y * inv0 + bb0.y;
    o[2] = acc0.z * inv0 + bb0.z;  o[3] = acc0.w * inv0 + bb0.w;
    o[4] = acc1.x * inv1 + bb1.x;  o[5] = acc1.y * inv1 + bb1.y;
    o[6] = acc1.z * inv1 + bb1.z;  o[7] = acc1.w * inv1 + bb1.w;
#pragma unroll
    for (int j = 0; j < 8; j++) o[j] = (o[j] > 0.f) ? o[j] : (__expf(o[j]) - 1.f);

    // GEMM2 partials: this lane's 8 out1 cols against W2^T rows
    float h2p[NCLS];
#pragma unroll
    for (int m = 0; m < NCLS; m++) {
        float4 wv0 = *(const float4*)&sW2t[m * 256 + lane * 4];
        float4 wv1 = *(const float4*)&sW2t[m * 256 + 128 + lane * 4];
        h2p[m] = o[0] * wv0.x + o[1] * wv0.y + o[2] * wv0.z + o[3] * wv0.w
               + o[4] * wv1.x + o[5] * wv1.y + o[6] * wv1.z + o[7] * wv1.w;
    }
    // butterfly reduce across 32 lanes -> all lanes hold the full h2 row
#pragma unroll
    for (int off = 16; off >= 1; off >>= 1)
#pragma unroll
        for (int m = 0; m < NCLS; m++)
            h2p[m] += __shfl_xor_sync(0xffffffffu, h2p[m], off);

    // att2 coefficients
    float s2 = 0.f, d2 = 0.f;
#pragma unroll
    for (int m = 0; m < NCLS; m++) {
        s2 = fmaf(h2p[m], sas2[m], s2);
        d2 = fmaf(h2p[m], sad2[m], d2);
    }
    if (lane == 0) { g_as2[warp] = s2; g_ad2[warp] = d2; }

    // store h2 row (lane j writes h2p[j])
    float sel = h2p[0];
#pragma unroll
    for (int m = 1; m < NCLS; m++) sel = (lane == m) ? h2p[m] : sel;
    if (lane < NCLS) g_h2[warp * NCLS + lane] = sel;
}

// ---------------- layer-2 softmax aggregation (1 warp / dst node) ----------------
__global__ void agg2_k(const float* __restrict__ b2, float* __restrict__ out, int N) {
    int warp = (blockIdx.x * blockDim.x + threadIdx.x) >> 5;
    if (warp >= N) return;
    int lane = threadIdx.x & 31;
    int s = g_start[warp], e = g_start[warp + 1];
    float adv = g_ad2[warp];

    float acc = 0.f, den = 0.f;
    for (int i = s; i < e; i++) {
        int2 se = g_csr[i];
        int src = se.x;
        float w = __int_as_float(se.y);
        float t = g_as2[src] + adv;
        t = (t > 0.f ? t : 0.2f * t) * w;
        float ex = __expf(t);
        den += ex;
        if (lane < NCLS) acc = fmaf(ex, g_h2[(size_t)src * NCLS + lane], acc);
    }
    if (lane < NCLS) out[(size_t)warp * NCLS + lane] = acc / (den + 1e-16f) + b2[lane];
}

// ---------------- launch ----------------
extern "C" void kernel_launch(void* const* d_in, const int* in_sizes, int n_in,
                              void* d_out, int out_size) {
    const float* x   = (const float*)d_in[0];
    const int*   ei  = (const int*)  d_in[1];
    const float* ew  = (const float*)d_in[2];
    const float* W1  = (const float*)d_in[3];
    const float* as1 = (const float*)d_in[4];
    const float* ad1 = (const float*)d_in[5];
    const float* b1  = (const float*)d_in[6];
    const float* W2  = (const float*)d_in[7];
    const float* as2 = (const float*)d_in[8];
    const float* ad2 = (const float*)d_in[9];
    const float* b2  = (const float*)d_in[10];
    float* out = (float*)d_out;

    int N  = in_sizes[0] / IN_CH;     // 20000
    int E  = in_sizes[2];             // 320000
    int ET = E + N;

    float *h1;
    cudaGetSymbolAddress((void**)&h1, g_h1);

    // --- CSR build ---
    zero_deg_k<<<(N + 255) / 256, 256>>>(N);
    hist_k<<<(ET + 255) / 256, 256>>>(ei, E, ET);
    scan_k<<<1, 1024>>>(N);
    scatter_k<<<(ET + 255) / 256, 256>>>(ei, ew, E, ET);

    // --- layer 1 ---
    {
        dim3 grid((N + 127) / 128, 2);
        sgemm_k<<<grid, 256>>>(x, W1, h1, N);
    }
    att1_k<<<(N * HEADS + 255) / 256, 256>>>(h1, as1, ad1, N);
    agg1_k<<<(N + 7) / 8, 256>>>(b1, W2, as2, ad2, N);   // fused agg1 + GEMM2 + att2

    // --- layer 2 ---
    agg2_k<<<(N + 7) / 8, 256>>>(b2, out, N);
}